// round 8
// baseline (speedup 1.0000x reference)
#include <cuda_runtime.h>
#include <math.h>

// ---------------------------------------------------------------------------
// CNN_51015621542651  —  R4 (5th submit; prior four hit GPU broker timeouts)
//  - oc-split x2 (blockIdx.z) on L0 and L1 conv: acc regs 48 -> 24,
//    occupancy up; gating moved to elementwise combine kernels.
//  - L1 ic-split x4 (blockIdx.y), L2 ic-split x10 (combined in head).
// ---------------------------------------------------------------------------

#define N_RAD 3

__device__ float gB[N_RAD * 125];
__device__ float gK0[23 * 1 * 125];
__device__ float gK1[23 * 20 * 125];
__device__ float gK2[20 * 20 * 125];
__device__ float gP0[16 * 23 * 33 * 33 * 33];          // L0 raw
__device__ float gA0[16 * 20 * 33 * 33 * 33];          // L0 gated
__device__ float gP1[4 * 16 * 23 * 18 * 18 * 18];      // L1 raw partials
__device__ float gA1[16 * 20 * 18 * 18 * 18];          // L1 gated
__device__ float gA2[10 * 16 * 20 * 1000];             // L2 partials

__device__ __forceinline__ float sigmoidf_(float x) {
    return 1.0f / (1.0f + expf(-x));
}

// ---------------------------------------------------------------------------
__global__ void init_basis_k() {
    __shared__ float sB[N_RAD * 125];
    __shared__ float sNorm[N_RAD];
    int t = threadIdx.x;
    if (t < 125) {
        int z = t / 25, y = (t / 5) % 5, x = t % 5;
        float dz = (float)z - 2.0f, dy = (float)y - 2.0f, dx = (float)x - 2.0f;
        float r = sqrtf(dx * dx + dy * dy + dz * dz);
        #pragma unroll
        for (int j = 0; j < N_RAD; j++) {
            float d = (r - (float)j) * (1.0f / 0.6f);
            sB[j * 125 + t] = expf(-0.5f * d * d);
        }
    }
    __syncthreads();
    if (t < N_RAD) {
        float s = 0.0f;
        for (int i = 0; i < 125; i++) { float v = sB[t * 125 + i]; s += v * v; }
        sNorm[t] = rsqrtf(s);
    }
    __syncthreads();
    if (t < 125) {
        #pragma unroll
        for (int j = 0; j < N_RAD; j++)
            gB[j * 125 + t] = sB[j * 125 + t] * sNorm[j];
    }
}

__global__ void synth_k(const float* __restrict__ W0,
                        const float* __restrict__ W1,
                        const float* __restrict__ W2) {
    int i = blockIdx.x * blockDim.x + threadIdx.x;
    if (i < 2875) {
        int t = i % 125, oc = i / 125;
        float s = 0.0f;
        #pragma unroll
        for (int j = 0; j < N_RAD; j++) s += W0[oc * 3 + j] * gB[j * 125 + t];
        gK0[i] = s;
    } else if (i < 2875 + 57500) {
        int k = i - 2875;
        int t = k % 125, rest = k / 125;
        int ic = rest % 20, oc = rest / 20;
        float s = 0.0f;
        #pragma unroll
        for (int j = 0; j < N_RAD; j++) s += W1[(oc * 20 + ic) * 3 + j] * gB[j * 125 + t];
        gK1[k] = s;
    } else if (i < 110375) {
        int k = i - 60375;
        int t = k % 125, rest = k / 125;
        int ic = rest % 20, oc = rest / 20;
        float s = 0.0f;
        #pragma unroll
        for (int j = 0; j < N_RAD; j++) s += W2[(oc * 20 + ic) * 3 + j] * gB[j * 125 + t];
        gK2[k] = s;
    }
}

// ---------------------------------------------------------------------------
// Conv3d stride 2, pad 3, k=5; thread computes 2 adjacent x-outputs.
//  blockIdx.y = ic-group (ICG channels each), blockIdx.z = oc-group (OCG each)
//  Writes raw partials: out[g][b][oc_global][spatial], group stride given.
// ---------------------------------------------------------------------------
template <int IC_TOTAL, int ICG, int OCRAW, int OCG, int TD, int TH, int TW>
__global__ void __launch_bounds__(TD * TH * TW / 2)
conv_t2(const float* __restrict__ in,
        const float* __restrict__ Ks,
        float* __restrict__ out,
        int inD, int inH, int inW,
        int outD, int outH, int outW,
        int ntD, int ntH, int ntW,
        size_t outGroupStride) {
    constexpr int SD = 2 * TD + 3, SH = 2 * TH + 3, SW = 2 * TW + 3;
    constexpr int SWP = (SW + 3) & ~3;
    constexpr int TXT = TW / 2;
    constexpr int NT = TD * TH * TXT;
    constexpr int NQ = OCG / 4;

    __shared__ __align__(16) float sIn[SD * SH * SWP];
    __shared__ __align__(16) float sK[125 * OCG];

    int blk = blockIdx.x;
    int tw = blk % ntW; blk /= ntW;
    int th = blk % ntH; blk /= ntH;
    int td = blk % ntD;
    int b  = blk / ntD;
    const int icBegin = blockIdx.y * ICG;
    const int oc0 = blockIdx.z * OCG;

    const int oz0 = td * TD, oy0 = th * TH, ox0 = tw * TW;
    const int iz0 = 2 * oz0 - 3, iy0 = 2 * oy0 - 3, ix0 = 2 * ox0 - 3;

    const int tid = threadIdx.x;
    const int txl = tid % TXT;
    const int ty  = (tid / TXT) % TH;
    const int tz  = tid / (TXT * TH);

    float2 acc[OCG];
    #pragma unroll
    for (int oc = 0; oc < OCG; oc++) acc[oc] = make_float2(0.0f, 0.0f);

    const size_t inVol = (size_t)inD * inH * inW;
    const float* inB = in + (size_t)b * IC_TOTAL * inVol;

    for (int icl = 0; icl < ICG; icl++) {
        const int ic = icBegin + icl;
        const float* inC = inB + (size_t)ic * inVol;
        for (int i = tid; i < SD * SH * SWP; i += NT) {
            int x = i % SWP, y = (i / SWP) % SH, z = i / (SWP * SH);
            int gz = iz0 + z, gy = iy0 + y, gx = ix0 + x;
            float v = 0.0f;
            if (x < SW && (unsigned)gz < (unsigned)inD &&
                (unsigned)gy < (unsigned)inH && (unsigned)gx < (unsigned)inW)
                v = inC[((size_t)gz * inH + gy) * inW + gx];
            sIn[i] = v;
        }
        for (int i = tid; i < 125 * OCG; i += NT) {
            int oc = i % OCG, t = i / OCG;
            int g = oc0 + oc;
            sK[i] = (g < OCRAW)
                        ? Ks[((size_t)g * IC_TOTAL + ic) * 125 + t]
                        : 0.0f;
        }
        __syncthreads();

        const float* rowBase =
            &sIn[(2 * tz) * (SH * SWP) + (2 * ty) * SWP + 4 * txl];
        #pragma unroll 1
        for (int kz = 0; kz < 5; kz++) {
            #pragma unroll 1
            for (int ky = 0; ky < 5; ky++) {
                const float4* r4 =
                    (const float4*)(rowBase + (kz * SH + ky) * SWP);
                float4 f0 = r4[0], f1 = r4[1];
                float v[8] = {f0.x, f0.y, f0.z, f0.w, f1.x, f1.y, f1.z, f1.w};
                const float4* kp =
                    (const float4*)&sK[((kz * 5 + ky) * 5) * OCG];
                #pragma unroll
                for (int kx = 0; kx < 5; kx++) {
                    const float vA = v[kx];
                    const float vB = v[kx + 2];
                    #pragma unroll
                    for (int q = 0; q < NQ; q++) {
                        float4 k4 = kp[kx * NQ + q];
                        acc[4 * q + 0].x += k4.x * vA;
                        acc[4 * q + 0].y += k4.x * vB;
                        acc[4 * q + 1].x += k4.y * vA;
                        acc[4 * q + 1].y += k4.y * vB;
                        acc[4 * q + 2].x += k4.z * vA;
                        acc[4 * q + 2].y += k4.z * vB;
                        acc[4 * q + 3].x += k4.w * vA;
                        acc[4 * q + 3].y += k4.w * vB;
                    }
                }
            }
        }
        __syncthreads();
    }

    const int oz = oz0 + tz, oy = oy0 + ty, oxA = ox0 + 2 * txl;
    if (oz < outD && oy < outH) {
        const size_t vol = (size_t)outD * outH * outW;
        const bool wA = (oxA < outW), wB = (oxA + 1 < outW);
        const size_t spA = ((size_t)oz * outH + oy) * outW + oxA;
        float* ob = out + (size_t)blockIdx.y * outGroupStride +
                    (size_t)b * OCRAW * vol + spA;
        #pragma unroll
        for (int oc = 0; oc < OCG; oc++) {
            if (oc0 + oc < OCRAW) {
                if (wA) ob[(size_t)(oc0 + oc) * vol]     = acc[oc].x;
                if (wB) ob[(size_t)(oc0 + oc) * vol + 1] = acc[oc].y;
            }
        }
    }
}

// ---------------------------------------------------------------------------
// Combine NG raw partials [NG,16,23,V] -> gated [16,20,V]
// ---------------------------------------------------------------------------
template <int V, int NG>
__global__ void combine_gate_k(const float* __restrict__ P,
                               float* __restrict__ out) {
    int idx = blockIdx.x * blockDim.x + threadIdx.x;
    if (idx >= 16 * V) return;
    int b = idx / V, sp = idx % V;
    float v[23];
    #pragma unroll
    for (int c = 0; c < 23; c++) {
        float s = 0.0f;
        #pragma unroll
        for (int g = 0; g < NG; g++)
            s += P[(((size_t)g * 16 + b) * 23 + c) * V + sp];
        v[c] = s;
    }
    float g0 = sigmoidf_(v[20]), g1 = sigmoidf_(v[21]), g2 = sigmoidf_(v[22]);
    float* ob = out + ((size_t)b * 20) * V + sp;
    #pragma unroll
    for (int c = 0; c < 20; c++) {
        float a = v[c];
        if (c < 5)       a = fmaxf(a, 0.0f);
        else if (c < 8)  a *= g0;
        else if (c < 13) a *= g1;
        else             a *= g2;
        ob[(size_t)c * V] = a;
    }
}

// ---------------------------------------------------------------------------
__global__ void head_k(const float* __restrict__ act,
                       const float* __restrict__ fc1w, const float* __restrict__ fc1b,
                       const float* __restrict__ fc2w, const float* __restrict__ fc2b,
                       float* __restrict__ out) {
    __shared__ float sm[20];
    __shared__ float sh[50];
    const int b = blockIdx.x;
    const int tid = threadIdx.x;

    {
        int c = tid >> 3, lane8 = tid & 7;
        float s = 0.0f;
        #pragma unroll
        for (int g = 0; g < 10; g++) {
            const float* p = act + (((size_t)g * 16 + b) * 20 + c) * 1000;
            for (int i = lane8; i < 1000; i += 8) s += p[i];
        }
        s += __shfl_down_sync(0xffffffffu, s, 4);
        s += __shfl_down_sync(0xffffffffu, s, 2);
        s += __shfl_down_sync(0xffffffffu, s, 1);
        if (lane8 == 0) sm[c] = s * (1.0f / 1000.0f);
    }
    __syncthreads();
    if (tid < 50) {
        float s = fc1b[tid];
        #pragma unroll
        for (int i = 0; i < 20; i++) s += sm[i] * fc1w[tid * 20 + i];
        sh[tid] = fmaxf(s, 0.0f);
    }
    __syncthreads();
    if (tid < 2) {
        float s = fc2b[tid];
        for (int i = 0; i < 50; i++) s += sh[i] * fc2w[tid * 50 + i];
        out[b * 2 + tid] = s;
    }
}

// ---------------------------------------------------------------------------
extern "C" void kernel_launch(void* const* d_in, const int* in_sizes, int n_in,
                              void* d_out, int out_size) {
    const float* inp   = (const float*)d_in[0];
    const float* W0    = (const float*)d_in[1];
    const float* W1    = (const float*)d_in[2];
    const float* W2    = (const float*)d_in[3];
    const float* fc1_w = (const float*)d_in[4];
    const float* fc1_b = (const float*)d_in[5];
    const float* fc2_w = (const float*)d_in[6];
    const float* fc2_b = (const float*)d_in[7];
    float* out = (float*)d_out;

    float *pK0, *pK1, *pK2, *pP0, *pA0, *pP1, *pA1, *pA2;
    cudaGetSymbolAddress((void**)&pK0, gK0);
    cudaGetSymbolAddress((void**)&pK1, gK1);
    cudaGetSymbolAddress((void**)&pK2, gK2);
    cudaGetSymbolAddress((void**)&pP0, gP0);
    cudaGetSymbolAddress((void**)&pA0, gA0);
    cudaGetSymbolAddress((void**)&pP1, gP1);
    cudaGetSymbolAddress((void**)&pA1, gA1);
    cudaGetSymbolAddress((void**)&pA2, gA2);

    init_basis_k<<<1, 128>>>();
    synth_k<<<(110375 + 255) / 256, 256>>>(W0, W1, W2);

    // L0: out 33^3, tile (4,8,8), oc-split x2 -> 3600x1x2 blocks x 128 thr
    conv_t2<1, 1, 23, 12, 4, 8, 8>
        <<<dim3(16 * 9 * 5 * 5, 1, 2), 4 * 8 * 4>>>(
            inp, pK0, pP0, 64, 64, 64, 33, 33, 33, 9, 5, 5, 0);
    combine_gate_k<33 * 33 * 33, 1>
        <<<(16 * 33 * 33 * 33 + 255) / 256, 256>>>(pP0, pA0);

    // L1: out 18^3, tile (6,6,6), ic x4, oc x2 -> 432x4x2 blocks x 108 thr
    conv_t2<20, 5, 23, 12, 6, 6, 6>
        <<<dim3(16 * 27, 4, 2), 6 * 6 * 3>>>(
            pA0, pK1, pP1, 33, 33, 33, 18, 18, 18, 3, 3, 3,
            (size_t)16 * 23 * 18 * 18 * 18);
    combine_gate_k<18 * 18 * 18, 4>
        <<<(16 * 18 * 18 * 18 + 255) / 256, 256>>>(pP1, pA1);

    // L2: out 10^3, tile (5,5,10), ic x10 -> 64x10 blocks x 125 thr
    conv_t2<20, 2, 20, 20, 5, 5, 10>
        <<<dim3(16 * 4, 10, 1), 5 * 5 * 5>>>(
            pA1, pK2, pA2, 18, 18, 18, 10, 10, 10, 2, 2, 1,
            (size_t)16 * 20 * 1000);

    head_k<<<16, 160>>>(pA2, fc1_w, fc1_b, fc2_w, fc2_b, out);
}

// round 14
// speedup vs baseline: 3.1883x; 3.1883x over previous
#include <cuda_runtime.h>
#include <math.h>

// ---------------------------------------------------------------------------
// CNN_51015621542651  —  R9 (6th submit; broker timeouts on prior attempts)
// Radial-basis factorization:
//   conv(x, K) with K[o,i] = sum_j W[o,i,j] B_j  ==>
//     Y[b,i,j] = conv3d(x[b,i], B_j)          (3 shared 125-tap kernels)
//     out[b,o] = sum_{i,j} W[o,i,j] Y[b,i,j]  (1x1 GEMM + gating)
// Work drops ~6.5x (15.6 -> 2.4 GFLOP); conv kernel needs only 6 acc regs.
// ---------------------------------------------------------------------------

#define N_RAD 3

__device__ float gB[N_RAD * 125];               // normalized radial basis
__device__ float gY0[16 * 1 * 3 * 33 * 33 * 33];   // L0 basis-conv out
__device__ float gA0[16 * 20 * 33 * 33 * 33];      // L0 gated
__device__ float gY1[16 * 20 * 3 * 18 * 18 * 18];  // L1 basis-conv out
__device__ float gA1[16 * 20 * 18 * 18 * 18];      // L1 gated
__device__ float gY2[16 * 20 * 3 * 1000];          // L2 basis-conv out
__device__ float gA2[16 * 20 * 1000];              // L2 raw out

__device__ __forceinline__ float sigmoidf_(float x) {
    return 1.0f / (1.0f + expf(-x));
}

// ---------------------------------------------------------------------------
__global__ void init_basis_k() {
    __shared__ float sB[N_RAD * 125];
    __shared__ float sNorm[N_RAD];
    int t = threadIdx.x;
    if (t < 125) {
        int z = t / 25, y = (t / 5) % 5, x = t % 5;
        float dz = (float)z - 2.0f, dy = (float)y - 2.0f, dx = (float)x - 2.0f;
        float r = sqrtf(dx * dx + dy * dy + dz * dz);
        #pragma unroll
        for (int j = 0; j < N_RAD; j++) {
            float d = (r - (float)j) * (1.0f / 0.6f);
            sB[j * 125 + t] = expf(-0.5f * d * d);
        }
    }
    __syncthreads();
    if (t < N_RAD) {
        float s = 0.0f;
        for (int i = 0; i < 125; i++) { float v = sB[t * 125 + i]; s += v * v; }
        sNorm[t] = rsqrtf(s);
    }
    __syncthreads();
    if (t < 125) {
        #pragma unroll
        for (int j = 0; j < N_RAD; j++)
            gB[j * 125 + t] = sB[j * 125 + t] * sNorm[j];
    }
}

// ---------------------------------------------------------------------------
// Basis conv: one (b, ic, spatial-tile) per block; 3 basis kernels at once.
// Stride 2, pad 3, k=5; each thread computes 2 adjacent x-outputs.
// Output: Y[((b*IC + ic)*3 + j)*vol + sp]
// ---------------------------------------------------------------------------
template <int TD, int TH, int TW>
__global__ void __launch_bounds__(TD * TH * TW / 2)
basis_conv_k(const float* __restrict__ in, float* __restrict__ Y,
             int IC,
             int inD, int inH, int inW,
             int outD, int outH, int outW,
             int ntD, int ntH, int ntW) {
    constexpr int SD = 2 * TD + 3, SH = 2 * TH + 3, SW = 2 * TW + 3;
    constexpr int SWP = (SW + 3) & ~3;
    constexpr int TXT = TW / 2;
    constexpr int NT = TD * TH * TXT;

    __shared__ __align__(16) float sIn[SD * SH * SWP];
    __shared__ __align__(16) float sB4[125 * 4];   // tap-major, j padded to 4

    int blk = blockIdx.x;
    int tw = blk % ntW; blk /= ntW;
    int th = blk % ntH; blk /= ntH;
    int td = blk % ntD;
    int icb = blk / ntD;           // b*IC + ic

    const int oz0 = td * TD, oy0 = th * TH, ox0 = tw * TW;
    const int iz0 = 2 * oz0 - 3, iy0 = 2 * oy0 - 3, ix0 = 2 * ox0 - 3;

    const int tid = threadIdx.x;
    const int txl = tid % TXT;
    const int ty  = (tid / TXT) % TH;
    const int tz  = tid / (TXT * TH);

    // stage basis (tap-major float4)
    for (int i = tid; i < 125 * 4; i += NT) {
        int j = i & 3, t = i >> 2;
        sB4[i] = (j < 3) ? gB[j * 125 + t] : 0.0f;
    }
    // stage input tile (zero-padded)
    const size_t inVol = (size_t)inD * inH * inW;
    const float* inC = in + (size_t)icb * inVol;
    for (int i = tid; i < SD * SH * SWP; i += NT) {
        int x = i % SWP, y = (i / SWP) % SH, z = i / (SWP * SH);
        int gz = iz0 + z, gy = iy0 + y, gx = ix0 + x;
        float v = 0.0f;
        if (x < SW && (unsigned)gz < (unsigned)inD &&
            (unsigned)gy < (unsigned)inH && (unsigned)gx < (unsigned)inW)
            v = inC[((size_t)gz * inH + gy) * inW + gx];
        sIn[i] = v;
    }
    __syncthreads();

    float2 a0 = make_float2(0.f, 0.f);
    float2 a1 = make_float2(0.f, 0.f);
    float2 a2 = make_float2(0.f, 0.f);

    const float* rowBase =
        &sIn[(2 * tz) * (SH * SWP) + (2 * ty) * SWP + 4 * txl];
    #pragma unroll 1
    for (int kz = 0; kz < 5; kz++) {
        #pragma unroll
        for (int ky = 0; ky < 5; ky++) {
            const float4* r4 = (const float4*)(rowBase + (kz * SH + ky) * SWP);
            float4 f0 = r4[0], f1 = r4[1];
            float v[8] = {f0.x, f0.y, f0.z, f0.w, f1.x, f1.y, f1.z, f1.w};
            const float4* kp = (const float4*)&sB4[((kz * 5 + ky) * 5) * 4];
            #pragma unroll
            for (int kx = 0; kx < 5; kx++) {
                float4 k4 = kp[kx];
                const float vA = v[kx];
                const float vB = v[kx + 2];
                a0.x += k4.x * vA;  a0.y += k4.x * vB;
                a1.x += k4.y * vA;  a1.y += k4.y * vB;
                a2.x += k4.z * vA;  a2.y += k4.z * vB;
            }
        }
    }

    const int oz = oz0 + tz, oy = oy0 + ty, oxA = ox0 + 2 * txl;
    if (oz < outD && oy < outH) {
        const size_t vol = (size_t)outD * outH * outW;
        const bool wA = (oxA < outW), wB = (oxA + 1 < outW);
        const size_t spA = ((size_t)oz * outH + oy) * outW + oxA;
        float* yb = Y + ((size_t)icb * 3) * vol + spA;
        if (wA) {
            yb[0 * vol] = a0.x; yb[1 * vol] = a1.x; yb[2 * vol] = a2.x;
        }
        if (wB) {
            yb[0 * vol + 1] = a0.y; yb[1 * vol + 1] = a1.y; yb[2 * vol + 1] = a2.y;
        }
    }
}

// ---------------------------------------------------------------------------
// 1x1 GEMM over k = ic*3+j, optional capsule gating.
//  Y: [16, KTOT, vol]   W: [OCRAW, KTOT] row-major   out: [16, OCOUT, vol]
// ---------------------------------------------------------------------------
template <int KTOT, bool GATED, int OCRAW>
__global__ void gemm_gate_k(const float* __restrict__ Y,
                            const float* __restrict__ W,
                            float* __restrict__ out, int vol) {
    constexpr int OC_PAD = (OCRAW + 3) & ~3;
    constexpr int NQ = OC_PAD / 4;
    __shared__ __align__(16) float sW[KTOT * OC_PAD];

    for (int i = threadIdx.x; i < KTOT * OC_PAD; i += blockDim.x) {
        int oc = i % OC_PAD, k = i / OC_PAD;
        sW[i] = (oc < OCRAW) ? W[oc * KTOT + k] : 0.0f;
    }
    __syncthreads();

    int idx = blockIdx.x * blockDim.x + threadIdx.x;
    if (idx >= 16 * vol) return;
    int b = idx / vol, sp = idx % vol;

    const float* yp = Y + (size_t)b * KTOT * vol + sp;
    float acc[OC_PAD];
    #pragma unroll
    for (int i = 0; i < OC_PAD; i++) acc[i] = 0.0f;

    #pragma unroll 6
    for (int k = 0; k < KTOT; k++) {
        float yv = yp[(size_t)k * vol];
        const float4* w4 = (const float4*)&sW[k * OC_PAD];
        #pragma unroll
        for (int q = 0; q < NQ; q++) {
            float4 w = w4[q];
            acc[4 * q + 0] += w.x * yv;
            acc[4 * q + 1] += w.y * yv;
            acc[4 * q + 2] += w.z * yv;
            acc[4 * q + 3] += w.w * yv;
        }
    }

    if constexpr (GATED) {
        float g0 = sigmoidf_(acc[20]);
        float g1 = sigmoidf_(acc[21]);
        float g2 = sigmoidf_(acc[22]);
        float* ob = out + (size_t)b * 20 * vol + sp;
        #pragma unroll
        for (int c = 0; c < 20; c++) {
            float a = acc[c];
            if (c < 5)       a = fmaxf(a, 0.0f);
            else if (c < 8)  a *= g0;
            else if (c < 13) a *= g1;
            else             a *= g2;
            ob[(size_t)c * vol] = a;
        }
    } else {
        float* ob = out + (size_t)b * OCRAW * vol + sp;
        #pragma unroll
        for (int c = 0; c < OCRAW; c++)
            ob[(size_t)c * vol] = acc[c];
    }
}

// ---------------------------------------------------------------------------
// Head: spatial mean [16,20,1000] -> [16,20]; fc1(50)+relu; fc2(2)
// ---------------------------------------------------------------------------
__global__ void head_k(const float* __restrict__ act,
                       const float* __restrict__ fc1w, const float* __restrict__ fc1b,
                       const float* __restrict__ fc2w, const float* __restrict__ fc2b,
                       float* __restrict__ out) {
    __shared__ float sm[20];
    __shared__ float sh[50];
    const int b = blockIdx.x;
    const int tid = threadIdx.x;

    {
        int c = tid >> 3, lane8 = tid & 7;
        const float* p = act + ((size_t)b * 20 + c) * 1000;
        float s = 0.0f;
        for (int i = lane8; i < 1000; i += 8) s += p[i];
        s += __shfl_down_sync(0xffffffffu, s, 4);
        s += __shfl_down_sync(0xffffffffu, s, 2);
        s += __shfl_down_sync(0xffffffffu, s, 1);
        if (lane8 == 0) sm[c] = s * (1.0f / 1000.0f);
    }
    __syncthreads();
    if (tid < 50) {
        float s = fc1b[tid];
        #pragma unroll
        for (int i = 0; i < 20; i++) s += sm[i] * fc1w[tid * 20 + i];
        sh[tid] = fmaxf(s, 0.0f);
    }
    __syncthreads();
    if (tid < 2) {
        float s = fc2b[tid];
        for (int i = 0; i < 50; i++) s += sh[i] * fc2w[tid * 50 + i];
        out[b * 2 + tid] = s;
    }
}

// ---------------------------------------------------------------------------
extern "C" void kernel_launch(void* const* d_in, const int* in_sizes, int n_in,
                              void* d_out, int out_size) {
    const float* inp   = (const float*)d_in[0];
    const float* W0    = (const float*)d_in[1];
    const float* W1    = (const float*)d_in[2];
    const float* W2    = (const float*)d_in[3];
    const float* fc1_w = (const float*)d_in[4];
    const float* fc1_b = (const float*)d_in[5];
    const float* fc2_w = (const float*)d_in[6];
    const float* fc2_b = (const float*)d_in[7];
    float* out = (float*)d_out;

    float *pY0, *pA0, *pY1, *pA1, *pY2, *pA2;
    cudaGetSymbolAddress((void**)&pY0, gY0);
    cudaGetSymbolAddress((void**)&pA0, gA0);
    cudaGetSymbolAddress((void**)&pY1, gY1);
    cudaGetSymbolAddress((void**)&pA1, gA1);
    cudaGetSymbolAddress((void**)&pY2, gY2);
    cudaGetSymbolAddress((void**)&pA2, gA2);

    init_basis_k<<<1, 128>>>();

    // L0 basis conv: in [16,1,64^3] -> Y0 [16,1,3,33^3]
    // tile (4,8,8) -> nt (9,5,5) = 225 tiles, 16 b*ic -> 3600 blocks x 128 thr
    basis_conv_k<4, 8, 8><<<225 * 16, 4 * 8 * 4>>>(
        inp, pY0, 1, 64, 64, 64, 33, 33, 33, 9, 5, 5);
    // G0: K=3 -> gated A0 [16,20,33^3]
    gemm_gate_k<3, true, 23><<<(16 * 35937 + 255) / 256, 256>>>(
        pY0, W0, pA0, 35937);

    // L1 basis conv: A0 -> Y1 [16,20,3,18^3]
    // tile (6,6,6) -> nt (3,3,3) = 27 tiles, 320 b*ic -> 8640 blocks x 108 thr
    basis_conv_k<6, 6, 6><<<27 * 16 * 20, 6 * 6 * 3>>>(
        pA0, pY1, 20, 33, 33, 33, 18, 18, 18, 3, 3, 3);
    // G1: K=60 -> gated A1 [16,20,18^3]
    gemm_gate_k<60, true, 23><<<(16 * 5832 + 255) / 256, 256>>>(
        pY1, W1, pA1, 5832);

    // L2 basis conv: A1 -> Y2 [16,20,3,10^3]
    // tile (5,5,10) -> nt (2,2,1) = 4 tiles, 320 b*ic -> 1280 blocks x 125 thr
    basis_conv_k<5, 5, 10><<<4 * 16 * 20, 5 * 5 * 5>>>(
        pA1, pY2, 20, 18, 18, 18, 10, 10, 10, 2, 2, 1);
    // G2: K=60 -> raw A2 [16,20,1000]
    gemm_gate_k<60, false, 20><<<(16 * 1000 + 255) / 256, 256>>>(
        pY2, W2, pA2, 1000);

    head_k<<<16, 160>>>(pA2, fc1_w, fc1_b, fc2_w, fc2_b, out);
}

// round 15
// speedup vs baseline: 3.5695x; 1.1196x over previous
#include <cuda_runtime.h>
#include <math.h>

// ---------------------------------------------------------------------------
// CNN_51015621542651  —  R15
// R9 factorization + conv upgrades:
//  - smem y-stride 20 floats (odd x4) -> conflict-free-ish input LDS.128
//  - 2x2 (z,x) register tiling: 4 outputs/thread, basis loads amortized 2x
//  - shift-only staging indices (padded pow2 loop) + float4 smem stores
// ---------------------------------------------------------------------------

#define N_RAD 3

__device__ float gB[N_RAD * 125];               // normalized radial basis
__device__ float gY0[16 * 1 * 3 * 33 * 33 * 33];   // L0 basis-conv out
__device__ float gA0[16 * 20 * 33 * 33 * 33];      // L0 gated
__device__ float gY1[16 * 20 * 3 * 18 * 18 * 18];  // L1 basis-conv out
__device__ float gA1[16 * 20 * 18 * 18 * 18];      // L1 gated
__device__ float gY2[16 * 20 * 3 * 1000];          // L2 basis-conv out
__device__ float gA2[16 * 20 * 1000];              // L2 raw out

__device__ __forceinline__ float sigmoidf_(float x) {
    return 1.0f / (1.0f + expf(-x));
}

// ---------------------------------------------------------------------------
__global__ void init_basis_k() {
    __shared__ float sB[N_RAD * 125];
    __shared__ float sNorm[N_RAD];
    int t = threadIdx.x;
    if (t < 125) {
        int z = t / 25, y = (t / 5) % 5, x = t % 5;
        float dz = (float)z - 2.0f, dy = (float)y - 2.0f, dx = (float)x - 2.0f;
        float r = sqrtf(dx * dx + dy * dy + dz * dz);
        #pragma unroll
        for (int j = 0; j < N_RAD; j++) {
            float d = (r - (float)j) * (1.0f / 0.6f);
            sB[j * 125 + t] = expf(-0.5f * d * d);
        }
    }
    __syncthreads();
    if (t < N_RAD) {
        float s = 0.0f;
        for (int i = 0; i < 125; i++) { float v = sB[t * 125 + i]; s += v * v; }
        sNorm[t] = rsqrtf(s);
    }
    __syncthreads();
    if (t < 125) {
        #pragma unroll
        for (int j = 0; j < N_RAD; j++)
            gB[j * 125 + t] = sB[j * 125 + t] * sNorm[j];
    }
}

// ---------------------------------------------------------------------------
// Basis conv, z2/x2 register tiling. One (b*IC+ic, spatial tile) per block.
// Each thread computes outputs (2tz,2tz+1) x (ty) x (2tx,2tx+1) for 3 bases.
// Requires: TD,TW even; SH = 2*TH+3 <= 16.
// Output layout: Y[(icb*3 + j)*vol + sp]
// ---------------------------------------------------------------------------
template <int TD, int TH, int TW>
__global__ void __launch_bounds__((TD / 2) * TH * (TW / 2))
basis_conv2_k(const float* __restrict__ in, float* __restrict__ Y,
              int inD, int inH, int inW,
              int outD, int outH, int outW,
              int ntD, int ntH, int ntW) {
    constexpr int SD = 2 * TD + 3, SH = 2 * TH + 3, SW = 2 * TW + 3;
    static_assert(SH <= 16, "staging loop assumes SH <= 16");
    constexpr int SY = ((SW + 3) & ~3) + 4;     // odd multiple of 4 (bank pad)
    constexpr int SZ = SY * SH;
    constexpr int TZT = TD / 2, TXT = TW / 2;
    constexpr int NT = TZT * TH * TXT;

    __shared__ __align__(16) float sIn[SD * SZ];
    __shared__ __align__(16) float sB4[125 * 4];   // tap-major, j padded to 4

    int blk = blockIdx.x;
    int tw = blk % ntW; blk /= ntW;
    int th = blk % ntH; blk /= ntH;
    int td = blk % ntD;
    int icb = blk / ntD;           // b*IC + ic

    const int oz0 = td * TD, oy0 = th * TH, ox0 = tw * TW;
    const int iz0 = 2 * oz0 - 3, iy0 = 2 * oy0 - 3, ix0 = 2 * ox0 - 3;

    const int tid = threadIdx.x;
    const int txl = tid % TXT;
    const int ty  = (tid / TXT) % TH;
    const int tzl = tid / (TXT * TH);

    // stage basis (tap-major float4)
    for (int i = tid; i < 125 * 4; i += NT) {
        int j = i & 3, t = i >> 2;
        sB4[i] = (j < 3) ? gB[j * 125 + t] : 0.0f;
    }

    // stage input tile: iterate float4 groups over padded (z, y16, g4) space
    const size_t inVol = (size_t)inD * inH * inW;
    const float* inC = in + (size_t)icb * inVol;
    for (int j = tid; j < SD * 16 * 4; j += NT) {
        int g = j & 3;            // float4 group in row (x = 4g..4g+3)
        int y = (j >> 2) & 15;
        int z = j >> 6;
        if (y >= SH) continue;
        float4 v = make_float4(0.f, 0.f, 0.f, 0.f);
        int gz = iz0 + z, gy = iy0 + y;
        if ((unsigned)gz < (unsigned)inD && (unsigned)gy < (unsigned)inH) {
            const float* row = inC + ((size_t)gz * inH + gy) * inW;
            int xb = 4 * g;
            int gx0 = ix0 + xb;
            float* pv = &v.x;
            #pragma unroll
            for (int e = 0; e < 4; e++) {
                int x = xb + e;
                int gx = gx0 + e;
                if (x < SW && (unsigned)gx < (unsigned)inW) pv[e] = row[gx];
            }
        }
        *(float4*)&sIn[z * SZ + y * SY + 4 * g] = v;
    }
    __syncthreads();

    float a0[4] = {0.f, 0.f, 0.f, 0.f};   // basis j=0: z0x0 z0x1 z1x0 z1x1
    float a1[4] = {0.f, 0.f, 0.f, 0.f};
    float a2[4] = {0.f, 0.f, 0.f, 0.f};

    const float* base = sIn + (2 * ty) * SY + 4 * txl + (4 * tzl) * SZ;
    #pragma unroll 1
    for (int kz = 0; kz < 5; kz++) {
        const float* p0 = base + kz * SZ;           // input rows for out z0
        const float* p1 = base + (kz + 2) * SZ;     // input rows for out z1
        const float* bk = sB4 + kz * 5 * 5 * 4;
        #pragma unroll
        for (int ky = 0; ky < 5; ky++) {
            float4 u0 = *(const float4*)(p0 + ky * SY);
            float4 u1 = *(const float4*)(p0 + ky * SY + 4);
            float4 w0 = *(const float4*)(p1 + ky * SY);
            float4 w1 = *(const float4*)(p1 + ky * SY + 4);
            float vz0[8] = {u0.x, u0.y, u0.z, u0.w, u1.x, u1.y, u1.z, u1.w};
            float vz1[8] = {w0.x, w0.y, w0.z, w0.w, w1.x, w1.y, w1.z, w1.w};
            const float4* kp = (const float4*)(bk + ky * 5 * 4);
            #pragma unroll
            for (int kx = 0; kx < 5; kx++) {
                float4 k4 = kp[kx];
                float pA = vz0[kx], pB = vz0[kx + 2];
                float qA = vz1[kx], qB = vz1[kx + 2];
                a0[0] += k4.x * pA;  a0[1] += k4.x * pB;
                a0[2] += k4.x * qA;  a0[3] += k4.x * qB;
                a1[0] += k4.y * pA;  a1[1] += k4.y * pB;
                a1[2] += k4.y * qA;  a1[3] += k4.y * qB;
                a2[0] += k4.z * pA;  a2[1] += k4.z * pB;
                a2[2] += k4.z * qA;  a2[3] += k4.z * qB;
            }
        }
    }

    const int oy = oy0 + ty;
    if (oy < outH) {
        const size_t vol = (size_t)outD * outH * outW;
        float* yb = Y + (size_t)icb * 3 * vol;
        const int ozA = oz0 + 2 * tzl;
        const int oxA = ox0 + 2 * txl;
        #pragma unroll
        for (int dz = 0; dz < 2; dz++) {
            int oz = ozA + dz;
            if (oz >= outD) break;
            size_t sp = ((size_t)oz * outH + oy) * outW + oxA;
            #pragma unroll
            for (int dx = 0; dx < 2; dx++) {
                if (oxA + dx < outW) {
                    int s = dz * 2 + dx;
                    yb[0 * vol + sp + dx] = a0[s];
                    yb[1 * vol + sp + dx] = a1[s];
                    yb[2 * vol + sp + dx] = a2[s];
                }
            }
        }
    }
}

// ---------------------------------------------------------------------------
// 1x1 GEMM over k = ic*3+j, optional capsule gating.
// ---------------------------------------------------------------------------
template <int KTOT, bool GATED, int OCRAW>
__global__ void gemm_gate_k(const float* __restrict__ Y,
                            const float* __restrict__ W,
                            float* __restrict__ out, int vol) {
    constexpr int OC_PAD = (OCRAW + 3) & ~3;
    constexpr int NQ = OC_PAD / 4;
    __shared__ __align__(16) float sW[KTOT * OC_PAD];

    for (int i = threadIdx.x; i < KTOT * OC_PAD; i += blockDim.x) {
        int oc = i % OC_PAD, k = i / OC_PAD;
        sW[i] = (oc < OCRAW) ? W[oc * KTOT + k] : 0.0f;
    }
    __syncthreads();

    int idx = blockIdx.x * blockDim.x + threadIdx.x;
    if (idx >= 16 * vol) return;
    int b = idx / vol, sp = idx % vol;

    const float* yp = Y + (size_t)b * KTOT * vol + sp;
    float acc[OC_PAD];
    #pragma unroll
    for (int i = 0; i < OC_PAD; i++) acc[i] = 0.0f;

    #pragma unroll 6
    for (int k = 0; k < KTOT; k++) {
        float yv = yp[(size_t)k * vol];
        const float4* w4 = (const float4*)&sW[k * OC_PAD];
        #pragma unroll
        for (int q = 0; q < NQ; q++) {
            float4 w = w4[q];
            acc[4 * q + 0] += w.x * yv;
            acc[4 * q + 1] += w.y * yv;
            acc[4 * q + 2] += w.z * yv;
            acc[4 * q + 3] += w.w * yv;
        }
    }

    if constexpr (GATED) {
        float g0 = sigmoidf_(acc[20]);
        float g1 = sigmoidf_(acc[21]);
        float g2 = sigmoidf_(acc[22]);
        float* ob = out + (size_t)b * 20 * vol + sp;
        #pragma unroll
        for (int c = 0; c < 20; c++) {
            float a = acc[c];
            if (c < 5)       a = fmaxf(a, 0.0f);
            else if (c < 8)  a *= g0;
            else if (c < 13) a *= g1;
            else             a *= g2;
            ob[(size_t)c * vol] = a;
        }
    } else {
        float* ob = out + (size_t)b * OCRAW * vol + sp;
        #pragma unroll
        for (int c = 0; c < OCRAW; c++)
            ob[(size_t)c * vol] = acc[c];
    }
}

// ---------------------------------------------------------------------------
// Head: spatial mean [16,20,1000] -> [16,20]; fc1(50)+relu; fc2(2)
// ---------------------------------------------------------------------------
__global__ void head_k(const float* __restrict__ act,
                       const float* __restrict__ fc1w, const float* __restrict__ fc1b,
                       const float* __restrict__ fc2w, const float* __restrict__ fc2b,
                       float* __restrict__ out) {
    __shared__ float sm[20];
    __shared__ float sh[50];
    const int b = blockIdx.x;
    const int tid = threadIdx.x;

    {
        int c = tid >> 3, lane8 = tid & 7;
        const float* p = act + ((size_t)b * 20 + c) * 1000;
        float s = 0.0f;
        for (int i = lane8; i < 1000; i += 8) s += p[i];
        s += __shfl_down_sync(0xffffffffu, s, 4);
        s += __shfl_down_sync(0xffffffffu, s, 2);
        s += __shfl_down_sync(0xffffffffu, s, 1);
        if (lane8 == 0) sm[c] = s * (1.0f / 1000.0f);
    }
    __syncthreads();
    if (tid < 50) {
        float s = fc1b[tid];
        #pragma unroll
        for (int i = 0; i < 20; i++) s += sm[i] * fc1w[tid * 20 + i];
        sh[tid] = fmaxf(s, 0.0f);
    }
    __syncthreads();
    if (tid < 2) {
        float s = fc2b[tid];
        for (int i = 0; i < 50; i++) s += sh[i] * fc2w[tid * 50 + i];
        out[b * 2 + tid] = s;
    }
}

// ---------------------------------------------------------------------------
extern "C" void kernel_launch(void* const* d_in, const int* in_sizes, int n_in,
                              void* d_out, int out_size) {
    const float* inp   = (const float*)d_in[0];
    const float* W0    = (const float*)d_in[1];
    const float* W1    = (const float*)d_in[2];
    const float* W2    = (const float*)d_in[3];
    const float* fc1_w = (const float*)d_in[4];
    const float* fc1_b = (const float*)d_in[5];
    const float* fc2_w = (const float*)d_in[6];
    const float* fc2_b = (const float*)d_in[7];
    float* out = (float*)d_out;

    float *pY0, *pA0, *pY1, *pA1, *pY2, *pA2;
    cudaGetSymbolAddress((void**)&pY0, gY0);
    cudaGetSymbolAddress((void**)&pA0, gA0);
    cudaGetSymbolAddress((void**)&pY1, gY1);
    cudaGetSymbolAddress((void**)&pA1, gA1);
    cudaGetSymbolAddress((void**)&pY2, gY2);
    cudaGetSymbolAddress((void**)&pA2, gA2);

    init_basis_k<<<1, 128>>>();

    // L0: in [16,1,64^3] -> Y0 [16,1,3,33^3]
    // tile (12,6,6): nt (3,6,6)=108, grid 108*16=1728, 108 thr, smem ~32.4KB
    basis_conv2_k<12, 6, 6><<<108 * 16, 6 * 6 * 3>>>(
        inp, pY0, 64, 64, 64, 33, 33, 33, 3, 6, 6);
    gemm_gate_k<3, true, 23><<<(16 * 35937 + 255) / 256, 256>>>(
        pY0, W0, pA0, 35937);

    // L1: A0 [16,20,33^3] -> Y1 [16,20,3,18^3]
    // tile (18,6,6): nt (1,3,3)=9, grid 9*320=2880, 162 thr, smem ~46.8KB
    basis_conv2_k<18, 6, 6><<<9 * 16 * 20, 9 * 6 * 3>>>(
        pA0, pY1, 33, 33, 33, 18, 18, 18, 1, 3, 3);
    gemm_gate_k<60, true, 23><<<(16 * 5832 + 255) / 256, 256>>>(
        pY1, W1, pA1, 5832);

    // L2: A1 [16,20,18^3] -> Y2 [16,20,3,10^3]
    // tile (10,6,6): nt (1,2,2)=4, grid 4*320=1280, 90 thr, smem ~27.6KB
    basis_conv2_k<10, 6, 6><<<4 * 16 * 20, 5 * 6 * 3>>>(
        pA1, pY2, 18, 18, 18, 10, 10, 10, 1, 2, 2);
    gemm_gate_k<60, false, 20><<<(16 * 1000 + 255) / 256, 256>>>(
        pY2, W2, pA2, 1000);

    head_k<<<16, 160>>>(pA2, fc1_w, fc1_b, fc2_w, fc2_b, out);
}